// round 4
// baseline (speedup 1.0000x reference)
#include <cuda_runtime.h>
#include <cstdint>
#include <cstddef>

// Problem constants
#define BSZ   32
#define TT    512
#define HH    512
#define G4    2048
#define GROUPS 4
#define GCTAS  32          // CTAs per group
#define BPG    8           // batches per group
#define NCTA  (GROUPS*GCTAS)
#define NTHR  256

// Static device scratch (allocation-free rule)
__device__ float g_xg[(size_t)TT * BSZ * G4];     // [T][B][4H]
__device__ float g_h[2][BSZ * HH];                // double-buffered h, [b][j]
__device__ unsigned g_bar4[GROUPS * 32];          // per-group barrier counters (128B apart)

// ---------- packed fp32x2 helpers ----------
__device__ __forceinline__ unsigned long long pack2(float lo, float hi) {
    unsigned long long r;
    asm("mov.b64 %0, {%1, %2};" : "=l"(r) : "f"(lo), "f"(hi));
    return r;
}
__device__ __forceinline__ void unpack2(unsigned long long v, float& lo, float& hi) {
    asm("mov.b64 {%0, %1}, %2;" : "=f"(lo), "=f"(hi) : "l"(v));
}
__device__ __forceinline__ void ffma2(unsigned long long& d,
                                      unsigned long long a,
                                      unsigned long long b) {
    asm("fma.rn.f32x2 %0, %1, %2, %0;" : "+l"(d) : "l"(a), "l"(b));
}

__device__ __forceinline__ float fast_sigmoid(float x) {
    return __fdividef(1.f, 1.f + __expf(-x));
}
__device__ __forceinline__ float fast_tanh(float x) {
    x = fminf(fmaxf(x, -15.f), 15.f);
    float e2 = __expf(-2.f * x);
    return __fdividef(1.f - e2, 1.f + e2);
}

// =====================================================================
// Phase 1: xg[t][b][g] = sum_d x[b,t,d]*W_ih[g,d] + b_ih[g] + b_hh[g]
// M=16384, N=2048, K=512.  BM=BN=128, BK=16, 8x8 microtile, fma2.
// =====================================================================
__global__ void __launch_bounds__(256) gemm_xg_kernel(
    const float* __restrict__ x,
    const float* __restrict__ Wih,
    const float* __restrict__ bih,
    const float* __restrict__ bhh)
{
    __shared__ float As[16][132];
    __shared__ float Bs[16][132];

    const int m0  = blockIdx.x * 128;
    const int n0  = blockIdx.y * 128;
    const int tid = threadIdx.x;
    const int tx  = tid & 15;
    const int ty  = tid >> 4;

    unsigned long long acc[8][4];
#pragma unroll
    for (int i = 0; i < 8; ++i)
#pragma unroll
        for (int p = 0; p < 4; ++p) acc[i][p] = 0ULL;

    for (int k0 = 0; k0 < 512; k0 += 16) {
#pragma unroll
        for (int s = 0; s < 2; ++s) {
            int idx = tid + s * 256;
            int row = idx >> 2;
            int cid = idx & 3;
            float4 va = *reinterpret_cast<const float4*>(
                &x[(size_t)(m0 + row) * 512 + k0 + cid * 4]);
            As[cid * 4 + 0][row] = va.x;
            As[cid * 4 + 1][row] = va.y;
            As[cid * 4 + 2][row] = va.z;
            As[cid * 4 + 3][row] = va.w;
            float4 vb = *reinterpret_cast<const float4*>(
                &Wih[(size_t)(n0 + row) * 512 + k0 + cid * 4]);
            Bs[cid * 4 + 0][row] = vb.x;
            Bs[cid * 4 + 1][row] = vb.y;
            Bs[cid * 4 + 2][row] = vb.z;
            Bs[cid * 4 + 3][row] = vb.w;
        }
        __syncthreads();
#pragma unroll
        for (int k = 0; k < 16; ++k) {
            float4 a0 = *reinterpret_cast<const float4*>(&As[k][ty * 8]);
            float4 a1 = *reinterpret_cast<const float4*>(&As[k][ty * 8 + 4]);
            ulonglong2 b0 = *reinterpret_cast<const ulonglong2*>(&Bs[k][tx * 8]);
            ulonglong2 b1 = *reinterpret_cast<const ulonglong2*>(&Bs[k][tx * 8 + 4]);
            unsigned long long aa[8];
            aa[0] = pack2(a0.x, a0.x); aa[1] = pack2(a0.y, a0.y);
            aa[2] = pack2(a0.z, a0.z); aa[3] = pack2(a0.w, a0.w);
            aa[4] = pack2(a1.x, a1.x); aa[5] = pack2(a1.y, a1.y);
            aa[6] = pack2(a1.z, a1.z); aa[7] = pack2(a1.w, a1.w);
#pragma unroll
            for (int i = 0; i < 8; ++i) {
                ffma2(acc[i][0], aa[i], b0.x);
                ffma2(acc[i][1], aa[i], b0.y);
                ffma2(acc[i][2], aa[i], b1.x);
                ffma2(acc[i][3], aa[i], b1.y);
            }
        }
        __syncthreads();
    }

    float bias[8];
#pragma unroll
    for (int j = 0; j < 8; ++j) {
        int n = n0 + tx * 8 + j;
        bias[j] = bih[n] + bhh[n];
    }
#pragma unroll
    for (int i = 0; i < 8; ++i) {
        int m = m0 + ty * 8 + i;
        int t = m & 511;
        int b = m >> 9;
        float o[8];
#pragma unroll
        for (int p = 0; p < 4; ++p) unpack2(acc[i][p], o[2 * p], o[2 * p + 1]);
#pragma unroll
        for (int j = 0; j < 8; ++j) o[j] += bias[j];
        float* dst = &g_xg[((size_t)t * 32 + b) * 2048 + n0 + tx * 8];
        *reinterpret_cast<float4*>(dst)     = make_float4(o[0], o[1], o[2], o[3]);
        *reinterpret_cast<float4*>(dst + 4) = make_float4(o[4], o[5], o[6], o[7]);
    }
}

// =====================================================================
// Phase 2: batch-grouped persistent recurrence.
// 4 groups x 32 CTAs. Group owns 8 batches; CTA owns 16 j (64 gate rows),
// full K=512, W_hh slice packed as f32x2 row-pairs in smem.
// Thread = (kq: K-quarter, cb: batch, rpg: row-octet). 4 ffma2 accs.
// Per-group release/acquire barrier (no threadfence / CCTL).
// =====================================================================

// smem layout:
//   Wp : ulonglong[512][32]          = 131072 B
//   Hs : float[8][536]               =  17152 B
//   Red: float[32][68]               =   8704 B
#define HS_STRIDE  536
#define RED_STRIDE 68
#define SMEM_REC_BYTES (131072 + 17152 + 8704)

__global__ void __launch_bounds__(256, 1) lstm_rec_kernel(
    const float* __restrict__ Whh,
    float* __restrict__ out)
{
    extern __shared__ char smraw[];
    unsigned long long* Wp = reinterpret_cast<unsigned long long*>(smraw);
    float* Hs  = reinterpret_cast<float*>(smraw + 131072);
    float* Red = reinterpret_cast<float*>(smraw + 131072 + 17152);

    const int tid   = threadIdx.x;
    const int group = blockIdx.x >> 5;          // 0..3
    const int rank  = blockIdx.x & 31;          // 0..31
    const int B0    = group * BPG;
    const int J0    = rank * 16;

    // ---- W preload: Wp[d][rp] packs gate rows (q*512+J0+2p, +1), rp=q*8+p ----
    for (int idx = tid; idx < 512 * 32; idx += NTHR) {
        int d  = idx >> 5;
        int rp = idx & 31;
        int q  = rp >> 3;
        int p  = rp & 7;
        int r0 = q * 512 + J0 + 2 * p;
        Wp[idx] = pack2(Whh[(size_t)r0 * 512 + d], Whh[(size_t)(r0 + 1) * 512 + d]);
    }

    const int kq  = tid >> 6;        // 0..3  K-quarter
    const int cb  = (tid >> 3) & 7;  // 0..7  batch (local)
    const int rpg = tid & 7;         // 0..7  row-octet (4 row-pairs)

    const int gb = tid >> 4;         // gate-thread batch (tid<128)
    const int jl = tid & 15;         // gate-thread j-local
    float c = 0.f;

    unsigned* bp = &g_bar4[group * 32];
    __syncthreads();

    for (int t = 0; t < TT; ++t) {
        // xg prefetch (independent of barrier — keep in flight)
        float xi = 0.f, xf = 0.f, xz = 0.f, xo = 0.f;
        if (tid < 128) {
            const float* xp = &g_xg[((size_t)t * 32 + B0 + gb) * 2048 + J0 + jl];
            xi = xp[0]; xf = xp[512]; xz = xp[1024]; xo = xp[1536];
        }

        if (t) {
            __syncthreads();       // all prior-step writes done (bar is cumulative)
            if (tid == 0) {
                unsigned ticket;
                asm volatile("atom.release.gpu.add.u32 %0, [%1], %2;"
                             : "=r"(ticket) : "l"(bp), "r"(1u) : "memory");
                unsigned target = (ticket / (unsigned)GCTAS + 1u) * (unsigned)GCTAS;
                unsigned cur;
                asm volatile("ld.acquire.gpu.u32 %0, [%1];"
                             : "=r"(cur) : "l"(bp) : "memory");
                while (cur < target) {
                    __nanosleep(32);
                    asm volatile("ld.acquire.gpu.u32 %0, [%1];"
                                 : "=r"(cur) : "l"(bp) : "memory");
                }
            }
            __syncthreads();

            // stage h_{t-1} for our 8 batches: 4096 floats
            const float* hsrc = g_h[(t + 1) & 1];
#pragma unroll
            for (int k2 = 0; k2 < 4; ++k2) {
                int f   = tid + k2 * 256;        // float4 index 0..1023
                int b   = f >> 7;
                int d4  = f & 127;
                float4 v = *reinterpret_cast<const float4*>(
                    &hsrc[(size_t)(B0 + b) * 512 + d4 * 4]);
                *reinterpret_cast<float4*>(&Hs[b * HS_STRIDE + d4 * 4]) = v;
            }
        } else {
#pragma unroll
            for (int k2 = 0; k2 < 4; ++k2) {
                int f  = tid + k2 * 256;
                int b  = f >> 7;
                int d4 = f & 127;
                *reinterpret_cast<float4*>(&Hs[b * HS_STRIDE + d4 * 4]) =
                    make_float4(0.f, 0.f, 0.f, 0.f);
            }
        }
        __syncthreads();

        // ---- partials: 4 row-pairs x 1 batch x K/4 ----
        unsigned long long acc0 = 0ULL, acc1 = 0ULL, acc2 = 0ULL, acc3 = 0ULL;
        const float* hrow = &Hs[cb * HS_STRIDE];
#pragma unroll 2
        for (int d = kq * 128; d < kq * 128 + 128; d += 4) {
            float4 hv = *reinterpret_cast<const float4*>(&hrow[d]);
            unsigned long long h0 = pack2(hv.x, hv.x);
            unsigned long long h1 = pack2(hv.y, hv.y);
            unsigned long long h2 = pack2(hv.z, hv.z);
            unsigned long long h3 = pack2(hv.w, hv.w);
            const ulonglong2* wb = reinterpret_cast<const ulonglong2*>(
                &Wp[(size_t)d * 32 + rpg * 4]);
            ulonglong2 wa, wc;
            wa = wb[0];  wc = wb[1];
            ffma2(acc0, h0, wa.x); ffma2(acc1, h0, wa.y);
            ffma2(acc2, h0, wc.x); ffma2(acc3, h0, wc.y);
            wa = wb[16]; wc = wb[17];
            ffma2(acc0, h1, wa.x); ffma2(acc1, h1, wa.y);
            ffma2(acc2, h1, wc.x); ffma2(acc3, h1, wc.y);
            wa = wb[32]; wc = wb[33];
            ffma2(acc0, h2, wa.x); ffma2(acc1, h2, wa.y);
            ffma2(acc2, h2, wc.x); ffma2(acc3, h2, wc.y);
            wa = wb[48]; wc = wb[49];
            ffma2(acc0, h3, wa.x); ffma2(acc1, h3, wa.y);
            ffma2(acc2, h3, wc.x); ffma2(acc3, h3, wc.y);
        }
        {
            float r0, r1, r2, r3, r4, r5, r6, r7;
            unpack2(acc0, r0, r1); unpack2(acc1, r2, r3);
            unpack2(acc2, r4, r5); unpack2(acc3, r6, r7);
            float* rdst = &Red[(kq * 8 + cb) * RED_STRIDE + rpg * 8];
            *reinterpret_cast<float4*>(rdst)     = make_float4(r0, r1, r2, r3);
            *reinterpret_cast<float4*>(rdst + 4) = make_float4(r4, r5, r6, r7);
        }
        __syncthreads();

        // ---- reduce + gates (128 threads: (gb, jl)) ----
        if (tid < 128) {
            float s0 = 0.f, s1 = 0.f, s2 = 0.f, s3 = 0.f;
#pragma unroll
            for (int k2 = 0; k2 < 4; ++k2) {
                const float* rr = &Red[(k2 * 8 + gb) * RED_STRIDE + jl];
                s0 += rr[0];
                s1 += rr[16];
                s2 += rr[32];
                s3 += rr[48];
            }
            float ig = fast_sigmoid(xi + s0);
            float fg = fast_sigmoid(xf + s1);
            float gg = fast_tanh(xz + s2);
            float og = fast_sigmoid(xo + s3);
            c = fg * c + ig * gg;
            float hval = og * fast_tanh(c);
            g_h[t & 1][(size_t)(B0 + gb) * 512 + J0 + jl] = hval;
            out[((size_t)(B0 + gb) * 512 + t) * 512 + J0 + jl] = fmaxf(hval, 0.f);
        }
    }
}

extern "C" void kernel_launch(void* const* d_in, const int* in_sizes, int n_in,
                              void* d_out, int out_size)
{
    const float* x   = (const float*)d_in[0];
    const float* Wih = (const float*)d_in[1];
    const float* Whh = (const float*)d_in[2];
    const float* bih = (const float*)d_in[3];
    const float* bhh = (const float*)d_in[4];
    float* out = (float*)d_out;

    dim3 g1(128, 16);
    gemm_xg_kernel<<<g1, 256>>>(x, Wih, bih, bhh);

    cudaFuncSetAttribute(lstm_rec_kernel,
                         cudaFuncAttributeMaxDynamicSharedMemorySize,
                         SMEM_REC_BYTES);
    lstm_rec_kernel<<<NCTA, NTHR, SMEM_REC_BYTES>>>(Whh, out);
}

// round 7
// speedup vs baseline: 2.2485x; 2.2485x over previous
#include <cuda_runtime.h>
#include <cstdint>
#include <cstddef>

// Problem constants
#define BSZ   32
#define TT    512
#define HH    512
#define G4    2048
#define GROUPS 4
#define GCTAS  32          // CTAs per group
#define BPG    8           // batches per group
#define NCTA  (GROUPS*GCTAS)
#define NTHR  512

// Static device scratch (allocation-free rule)
__device__ float g_xg[(size_t)TT * BSZ * G4];     // [T][B][4H]
__device__ float g_h[2][BSZ * HH];                // double-buffered h, [b][j]
__device__ unsigned g_bar4[GROUPS * 32];          // per-group barrier counters

// ---------- packed fp32x2 helpers ----------
__device__ __forceinline__ unsigned long long pack2(float lo, float hi) {
    unsigned long long r;
    asm("mov.b64 %0, {%1, %2};" : "=l"(r) : "f"(lo), "f"(hi));
    return r;
}
__device__ __forceinline__ void unpack2(unsigned long long v, float& lo, float& hi) {
    asm("mov.b64 {%0, %1}, %2;" : "=f"(lo), "=f"(hi) : "l"(v));
}
__device__ __forceinline__ void ffma2(unsigned long long& d,
                                      unsigned long long a,
                                      unsigned long long b) {
    asm("fma.rn.f32x2 %0, %1, %2, %0;" : "+l"(d) : "l"(a), "l"(b));
}

__device__ __forceinline__ float fast_sigmoid(float x) {
    return __fdividef(1.f, 1.f + __expf(-x));
}
__device__ __forceinline__ float fast_tanh(float x) {
    x = fminf(fmaxf(x, -15.f), 15.f);
    float e2 = __expf(-2.f * x);
    return __fdividef(1.f - e2, 1.f + e2);
}

// =====================================================================
// Phase 1: xg[t][b][g] = sum_d x[b,t,d]*W_ih[g,d] + b_ih[g] + b_hh[g]
// M=16384, N=2048, K=512.  BM=BN=128, BK=16, 8x8 microtile, fma2.
// (unchanged — passed R2/R4)
// =====================================================================
__global__ void __launch_bounds__(256) gemm_xg_kernel(
    const float* __restrict__ x,
    const float* __restrict__ Wih,
    const float* __restrict__ bih,
    const float* __restrict__ bhh)
{
    __shared__ float As[16][132];
    __shared__ float Bs[16][132];

    const int m0  = blockIdx.x * 128;
    const int n0  = blockIdx.y * 128;
    const int tid = threadIdx.x;
    const int tx  = tid & 15;
    const int ty  = tid >> 4;

    unsigned long long acc[8][4];
#pragma unroll
    for (int i = 0; i < 8; ++i)
#pragma unroll
        for (int p = 0; p < 4; ++p) acc[i][p] = 0ULL;

    for (int k0 = 0; k0 < 512; k0 += 16) {
#pragma unroll
        for (int s = 0; s < 2; ++s) {
            int idx = tid + s * 256;
            int row = idx >> 2;
            int cid = idx & 3;
            float4 va = *reinterpret_cast<const float4*>(
                &x[(size_t)(m0 + row) * 512 + k0 + cid * 4]);
            As[cid * 4 + 0][row] = va.x;
            As[cid * 4 + 1][row] = va.y;
            As[cid * 4 + 2][row] = va.z;
            As[cid * 4 + 3][row] = va.w;
            float4 vb = *reinterpret_cast<const float4*>(
                &Wih[(size_t)(n0 + row) * 512 + k0 + cid * 4]);
            Bs[cid * 4 + 0][row] = vb.x;
            Bs[cid * 4 + 1][row] = vb.y;
            Bs[cid * 4 + 2][row] = vb.z;
            Bs[cid * 4 + 3][row] = vb.w;
        }
        __syncthreads();
#pragma unroll
        for (int k = 0; k < 16; ++k) {
            float4 a0 = *reinterpret_cast<const float4*>(&As[k][ty * 8]);
            float4 a1 = *reinterpret_cast<const float4*>(&As[k][ty * 8 + 4]);
            ulonglong2 b0 = *reinterpret_cast<const ulonglong2*>(&Bs[k][tx * 8]);
            ulonglong2 b1 = *reinterpret_cast<const ulonglong2*>(&Bs[k][tx * 8 + 4]);
            unsigned long long aa[8];
            aa[0] = pack2(a0.x, a0.x); aa[1] = pack2(a0.y, a0.y);
            aa[2] = pack2(a0.z, a0.z); aa[3] = pack2(a0.w, a0.w);
            aa[4] = pack2(a1.x, a1.x); aa[5] = pack2(a1.y, a1.y);
            aa[6] = pack2(a1.z, a1.z); aa[7] = pack2(a1.w, a1.w);
#pragma unroll
            for (int i = 0; i < 8; ++i) {
                ffma2(acc[i][0], aa[i], b0.x);
                ffma2(acc[i][1], aa[i], b0.y);
                ffma2(acc[i][2], aa[i], b1.x);
                ffma2(acc[i][3], aa[i], b1.y);
            }
        }
        __syncthreads();
    }

    float bias[8];
#pragma unroll
    for (int j = 0; j < 8; ++j) {
        int n = n0 + tx * 8 + j;
        bias[j] = bih[n] + bhh[n];
    }
#pragma unroll
    for (int i = 0; i < 8; ++i) {
        int m = m0 + ty * 8 + i;
        int t = m & 511;
        int b = m >> 9;
        float o[8];
#pragma unroll
        for (int p = 0; p < 4; ++p) unpack2(acc[i][p], o[2 * p], o[2 * p + 1]);
#pragma unroll
        for (int j = 0; j < 8; ++j) o[j] += bias[j];
        float* dst = &g_xg[((size_t)t * 32 + b) * 2048 + n0 + tx * 8];
        *reinterpret_cast<float4*>(dst)     = make_float4(o[0], o[1], o[2], o[3]);
        *reinterpret_cast<float4*>(dst + 4) = make_float4(o[4], o[5], o[6], o[7]);
    }
}

// =====================================================================
// Phase 2: register-resident-W persistent recurrence, 512 threads/CTA.
// 4 groups x 32 CTAs. CTA owns 16 hidden j (64 gate rows), 8 batches.
// Thread (warp wid 0..15, lane sl): 4 rows x 16-d slice of W in registers
// (32 packed f32x2, ~110 regs total/thread). Per step: 8 batch passes of
// 32 ffma2 each; shfl_xor(16) + 16-slice smem reduce; gates on 128 threads.
// =====================================================================

// smem: Hs float[8*32*18] = 18432 B ; Red float[8*64*20] = 40960 B
#define HS_OFF   0
#define RED_OFF  18432
#define SMEM_REC_BYTES (18432 + 40960)

__global__ void __launch_bounds__(512, 1) lstm_rec_kernel(
    const float* __restrict__ Whh,
    float* __restrict__ out)
{
    extern __shared__ char smraw[];
    float* Hs  = reinterpret_cast<float*>(smraw + HS_OFF);   // [(b*32+sl)*18 + m]
    float* Red = reinterpret_cast<float*>(smraw + RED_OFF);  // [(b*64+lr)*20 + sl2]

    const int tid   = threadIdx.x;
    const int group = blockIdx.x >> 5;          // 0..3
    const int rank  = blockIdx.x & 31;          // 0..31
    const int B0    = group * BPG;
    const int J0    = rank * 16;
    const int wid   = tid >> 5;                 // warp 0..15 -> 4 gate rows each
    const int sl    = tid & 31;                 // lane -> 16-d K-slice

    // ---- W_hh into registers: wreg[r][k] = (W[row, sl*16+2k], W[row, sl*16+2k+1]) ----
    unsigned long long wreg[4][8];
#pragma unroll
    for (int r = 0; r < 4; ++r) {
        int lr   = wid * 4 + r;                 // local gate row 0..63
        int grow = (lr >> 4) * 512 + J0 + (lr & 15);
        const float2* wsrc = reinterpret_cast<const float2*>(
            &Whh[(size_t)grow * 512 + sl * 16]);
#pragma unroll
        for (int k = 0; k < 8; ++k) {
            float2 w2 = wsrc[k];
            wreg[r][k] = pack2(w2.x, w2.y);
        }
    }

    const int gb = tid >> 4;         // gate-thread batch (tid<128)
    const int jl = tid & 15;         // gate-thread hidden index (local)
    float c = 0.f;

    unsigned* bp = &g_bar4[group * 32];
    __syncthreads();

    for (int t = 0; t < TT; ++t) {
        // xg prefetch (independent of barrier)
        float xi = 0.f, xf = 0.f, xz = 0.f, xo = 0.f;
        if (tid < 128) {
            const float* xp = &g_xg[((size_t)t * 32 + B0 + gb) * 2048 + J0 + jl];
            xi = xp[0]; xf = xp[512]; xz = xp[1024]; xo = xp[1536];
        }

        if (t) {
            __syncthreads();       // CTA's own h/out writes done
            if (tid == 0) {
                unsigned ticket;
                asm volatile("atom.release.gpu.add.u32 %0, [%1], %2;"
                             : "=r"(ticket) : "l"(bp), "r"(1u) : "memory");
                unsigned target = (ticket / (unsigned)GCTAS + 1u) * (unsigned)GCTAS;
                unsigned cur;
                asm volatile("ld.acquire.gpu.u32 %0, [%1];"
                             : "=r"(cur) : "l"(bp) : "memory");
                while (cur < target) {
                    __nanosleep(32);
                    asm volatile("ld.acquire.gpu.u32 %0, [%1];"
                                 : "=r"(cur) : "l"(bp) : "memory");
                }
            }
            __syncthreads();

            // stage h_{t-1} for our 8 batches into sliced layout (4096 floats)
            const float* hsrc = g_h[(t + 1) & 1];
#pragma unroll
            for (int i = 0; i < 4; ++i) {
                int f   = tid + i * 512;        // float2 index 0..2047
                int b   = f >> 8;
                int rem = f & 255;
                int d   = rem * 2;
                int sli = d >> 4;
                int m   = d & 15;
                float2 v = *reinterpret_cast<const float2*>(
                    &hsrc[(size_t)(B0 + b) * 512 + d]);
                *reinterpret_cast<float2*>(&Hs[(b * 32 + sli) * 18 + m]) = v;
            }
        } else {
#pragma unroll
            for (int i = 0; i < 4; ++i) {
                int f   = tid + i * 512;
                int b   = f >> 8;
                int rem = f & 255;
                int d   = rem * 2;
                int sli = d >> 4;
                int m   = d & 15;
                *reinterpret_cast<float2*>(&Hs[(b * 32 + sli) * 18 + m]) =
                    make_float2(0.f, 0.f);
            }
        }
        __syncthreads();

        // ---- 8 batch passes: W from registers, h from smem ----
#pragma unroll
        for (int b = 0; b < 8; ++b) {
            const unsigned long long* hp =
                reinterpret_cast<const unsigned long long*>(
                    &Hs[(b * 32 + sl) * 18]);
            unsigned long long hb[8];
#pragma unroll
            for (int k = 0; k < 8; ++k) hb[k] = hp[k];

            unsigned long long acc[4];
#pragma unroll
            for (int r = 0; r < 4; ++r) acc[r] = 0ULL;
#pragma unroll
            for (int k = 0; k < 8; ++k) {
#pragma unroll
                for (int r = 0; r < 4; ++r) ffma2(acc[r], wreg[r][k], hb[k]);
            }
#pragma unroll
            for (int r = 0; r < 4; ++r) {
                float lo, hi;
                unpack2(acc[r], lo, hi);
                float s = lo + hi;
                s += __shfl_xor_sync(0xffffffffu, s, 16);
                if (sl < 16) Red[(b * 64 + wid * 4 + r) * 20 + sl] = s;
            }
        }
        __syncthreads();

        // ---- reduce 16 slice-pairs + gates (128 threads: (gb, jl)) ----
        if (tid < 128) {
            float sums[4];
#pragma unroll
            for (int q = 0; q < 4; ++q) {
                const float4* rr = reinterpret_cast<const float4*>(
                    &Red[(gb * 64 + q * 16 + jl) * 20]);
                float4 a = rr[0], bq = rr[1], cq = rr[2], dq = rr[3];
                sums[q] = ((a.x + a.y) + (a.z + a.w))
                        + ((bq.x + bq.y) + (bq.z + bq.w))
                        + ((cq.x + cq.y) + (cq.z + cq.w))
                        + ((dq.x + dq.y) + (dq.z + dq.w));
            }
            float ig = fast_sigmoid(xi + sums[0]);
            float fg = fast_sigmoid(xf + sums[1]);
            float gg = fast_tanh(xz + sums[2]);
            float og = fast_sigmoid(xo + sums[3]);
            c = fg * c + ig * gg;
            float hval = og * fast_tanh(c);
            g_h[t & 1][(size_t)(B0 + gb) * 512 + J0 + jl] = hval;
            out[((size_t)(B0 + gb) * 512 + t) * 512 + J0 + jl] = fmaxf(hval, 0.f);
        }
    }
}

extern "C" void kernel_launch(void* const* d_in, const int* in_sizes, int n_in,
                              void* d_out, int out_size)
{
    const float* x   = (const float*)d_in[0];
    const float* Wih = (const float*)d_in[1];
    const float* Whh = (const float*)d_in[2];
    const float* bih = (const float*)d_in[3];
    const float* bhh = (const float*)d_in[4];
    float* out = (float*)d_out;

    dim3 g1(128, 16);
    gemm_xg_kernel<<<g1, 256>>>(x, Wih, bih, bhh);

    cudaFuncSetAttribute(lstm_rec_kernel,
                         cudaFuncAttributeMaxDynamicSharedMemorySize,
                         SMEM_REC_BYTES);
    lstm_rec_kernel<<<NCTA, NTHR, SMEM_REC_BYTES>>>(Whh, out);
}